// round 13
// baseline (speedup 1.0000x reference)
#include <cuda_runtime.h>

#define NN 100000     // nodes
#define NE 1600000    // edges
#define INF 64        // input features
#define OF 40         // output features
#define NQ (OF / 4)   // 10 float4 quads per row
#define NC 10000      // clusters
#define SNB ((NN + 1023) / 1024)   // 98 scan blocks (tile = 256 thr * 4 items)

// ---- scratch (device globals; no dynamic allocation allowed) ----
__device__ __align__(16) float g_u[NN * OF];
__device__ __align__(16) float g_v[NN * OF];
__device__ __align__(16) int   g_deg[NN];     // in-edge histogram (no self loop)
__device__ __align__(16) float g_dinv[NN];    // rsqrt(deg+1)
__device__ __align__(16) int   g_off[NN];     // CSR row offsets (exclusive scan of deg)
__device__ __align__(16) int   g_cur[NN];     // scatter cursors
__device__ __align__(16) int   g_csr[NE];     // CSR column (source) indices
__device__ __align__(16) int   g_part[SNB];   // per-block totals
__device__ __align__(16) float g_xc[NC * OF];
__device__ __align__(16) int   g_cnt[NC];

__device__ __forceinline__ void red_add_v4(float* p, float4 v) {
    asm volatile("red.global.add.v4.f32 [%0], {%1,%2,%3,%4};"
                 :: "l"(p), "f"(v.x), "f"(v.y), "f"(v.z), "f"(v.w)
                 : "memory");
}

// zero deg/cnt/xc (kernel, not memset: must be IN the captured graph)
__global__ void k_init() {
    int i = blockIdx.x * blockDim.x + threadIdx.x;
    if (i < NN) g_deg[i] = 0;
    if (i < NC) g_cnt[i] = 0;
    if (i < NC * OF) g_xc[i] = 0.f;
}

__global__ void k_hist(const int* __restrict__ row, const int* __restrict__ cl) {
    int i = blockIdx.x * blockDim.x + threadIdx.x;
    if (i < NE) atomicAdd(&g_deg[__ldg(row + i)], 1);
    if (i < NN) atomicAdd(&g_cnt[__ldg(cl + i)], 1);
}

// Pass A: per-block exclusive offsets + block totals + dinv (deg already in regs).
__global__ void __launch_bounds__(256) k_scanA() {
    __shared__ int warp_sums[8];
    int lane = threadIdx.x & 31, wid = threadIdx.x >> 5;
    int idx = blockIdx.x * 1024 + threadIdx.x * 4;

    int4 d = make_int4(0, 0, 0, 0);
    if (idx + 3 < NN) d = *(const int4*)(g_deg + idx);
    else {
        if (idx < NN)     d.x = g_deg[idx];
        if (idx + 1 < NN) d.y = g_deg[idx + 1];
        if (idx + 2 < NN) d.z = g_deg[idx + 2];
    }
    int s3 = d.x + d.y + d.z + d.w;

    int v = s3;
#pragma unroll
    for (int o = 1; o < 32; o <<= 1) {
        int t = __shfl_up_sync(~0u, v, o);
        if (lane >= o) v += t;
    }
    if (lane == 31) warp_sums[wid] = v;
    __syncthreads();
    if (wid == 0) {
        int w = (lane < 8) ? warp_sums[lane] : 0;
#pragma unroll
        for (int o = 1; o < 8; o <<= 1) {
            int t = __shfl_up_sync(~0u, w, o);
            if (lane >= o) w += t;
        }
        if (lane < 8) warp_sums[lane] = w;
    }
    __syncthreads();
    int excl = (v - s3) + (wid ? warp_sums[wid - 1] : 0);

    int e0 = excl, e1 = e0 + d.x, e2 = e1 + d.y, e3 = e2 + d.z;
    if (idx + 3 < NN) {
        *(int4*)(g_off + idx) = make_int4(e0, e1, e2, e3);
        *(float4*)(g_dinv + idx) =
            make_float4(rsqrtf((float)(d.x + 1)), rsqrtf((float)(d.y + 1)),
                        rsqrtf((float)(d.z + 1)), rsqrtf((float)(d.w + 1)));
    } else {
        int ee[4] = {e0, e1, e2, e3};
        int dd[4] = {d.x, d.y, d.z, d.w};
        for (int t = 0; t < 4; t++)
            if (idx + t < NN) {
                g_off[idx + t] = ee[t];
                g_dinv[idx + t] = rsqrtf((float)(dd[t] + 1));
            }
    }
    if (threadIdx.x == 0) g_part[blockIdx.x] = warp_sums[7];
}

// Pass B: each block redundantly computes its base from the 98 partials,
// then finalizes g_off and g_cur.
__global__ void __launch_bounds__(256) k_scanB() {
    __shared__ int sh_part[SNB];
    __shared__ int sh_base;
    for (int t = threadIdx.x; t < SNB; t += blockDim.x) sh_part[t] = g_part[t];
    __syncthreads();
    if (threadIdx.x == 0) {
        int base = 0;
        for (int j = 0; j < (int)blockIdx.x; j++) base += sh_part[j];
        sh_base = base;
    }
    __syncthreads();
    int base = sh_base;
    int idx = blockIdx.x * 1024 + threadIdx.x * 4;
    if (idx + 3 < NN) {
        int4 o = *(const int4*)(g_off + idx);
        o.x += base; o.y += base; o.z += base; o.w += base;
        *(int4*)(g_off + idx) = o;
        *(int4*)(g_cur + idx) = o;
    } else {
        for (int t = 0; t < 4; t++)
            if (idx + t < NN) {
                int o = g_off[idx + t] + base;
                g_off[idx + t] = o;
                g_cur[idx + t] = o;
            }
    }
}

__global__ void k_scatter(const int* __restrict__ row, const int* __restrict__ col) {
    int i = blockIdx.x * blockDim.x + threadIdx.x;
    if (i >= NE) return;
    int r = __ldg(row + i);
    int pos = atomicAdd(&g_cur[r], 1);
    g_csr[pos] = __ldg(col + i);
}

// w = x @ W^T  (NO dinv — removed so this kernel depends only on x, W and can
// fork at t=0, fully hidden behind the CSR build; hop1 applies dinv[col]).
// R8-proven one-node f32x2 form.
__global__ void __launch_bounds__(128) k_transform(const float* __restrict__ x,
                                                   const float* __restrict__ W) {
    __shared__ float Wp[INF * OF];   // f-major: Wp[f*OF + o]
    for (int i = threadIdx.x; i < INF * OF; i += blockDim.x) {
        int f = i / OF, o = i - f * OF;
        Wp[i] = W[o * INF + f];
    }
    __syncthreads();
    int n = blockIdx.x * blockDim.x + threadIdx.x;
    if (n >= NN) return;

    unsigned long long acc[OF / 2];
#pragma unroll
    for (int p = 0; p < OF / 2; p++) acc[p] = 0ull;

    const float4* xp = (const float4*)(x + (size_t)n * INF);
#pragma unroll 1
    for (int fc = 0; fc < INF; fc += 8) {
        float4 a = __ldg(xp + fc / 4);
        float4 b2 = __ldg(xp + fc / 4 + 1);
        float xs[8] = {a.x, a.y, a.z, a.w, b2.x, b2.y, b2.z, b2.w};
#pragma unroll
        for (int ff = 0; ff < 8; ff++) {
            int f = fc + ff;
            unsigned long long xx;
            asm("mov.b64 %0, {%1, %1};" : "=l"(xx) : "f"(xs[ff]));
            const ulonglong2* wrow = (const ulonglong2*)(Wp + f * OF);
#pragma unroll
            for (int p = 0; p < NQ; p++) {
                ulonglong2 w = wrow[p];
                asm("fma.rn.f32x2 %0, %1, %2, %0;" : "+l"(acc[2 * p]) : "l"(w.x), "l"(xx));
                asm("fma.rn.f32x2 %0, %1, %2, %0;" : "+l"(acc[2 * p + 1]) : "l"(w.y), "l"(xx));
            }
        }
    }
    ulonglong2* up = (ulonglong2*)(g_u + (size_t)n * OF);
#pragma unroll
    for (int p = 0; p < NQ; p++) {
        ulonglong2 st; st.x = acc[2 * p]; st.y = acc[2 * p + 1];
        up[p] = st;
    }
}

// Gather hop. FIRST: input is raw w=xW, so each gathered row (and self) is
// scaled by dinv[src] inside the gather (FMA instead of ADD — free).
// DIR=0: g_u -> g_v.  DIR=1: g_v -> g_u.  LAST: -> cluster RED.
// 10 lanes per node (one float4 quad each), 32 nodes per 320-thread block.
template <int DIR, int LAST, int FIRST>
__global__ void __launch_bounds__(320) k_hop(const int* __restrict__ cl) {
    int tid = threadIdx.x;
    int g = tid / NQ;
    int q = tid - g * NQ;
    int n = blockIdx.x * 32 + g;
    if (n >= NN) return;

    const float4* base = (const float4*)(DIR ? g_v : g_u);
    int s = g_off[n];
    int e = s + g_deg[n];
    float dvn = g_dinv[n];

    float4 acc = __ldg(base + (size_t)n * NQ + q);  // self loop
    if (FIRST) { acc.x *= dvn; acc.y *= dvn; acc.z *= dvn; acc.w *= dvn; }

    int j = s;
    for (; j + 4 <= e; j += 4) {
        int c0 = __ldg(g_csr + j);
        int c1 = __ldg(g_csr + j + 1);
        int c2 = __ldg(g_csr + j + 2);
        int c3 = __ldg(g_csr + j + 3);
        float4 a = __ldg(base + (size_t)c0 * NQ + q);
        float4 b2 = __ldg(base + (size_t)c1 * NQ + q);
        float4 c = __ldg(base + (size_t)c2 * NQ + q);
        float4 d = __ldg(base + (size_t)c3 * NQ + q);
        if (FIRST) {
            float w0 = __ldg(g_dinv + c0), w1 = __ldg(g_dinv + c1);
            float w2 = __ldg(g_dinv + c2), w3 = __ldg(g_dinv + c3);
            acc.x += a.x * w0 + b2.x * w1 + c.x * w2 + d.x * w3;
            acc.y += a.y * w0 + b2.y * w1 + c.y * w2 + d.y * w3;
            acc.z += a.z * w0 + b2.z * w1 + c.z * w2 + d.z * w3;
            acc.w += a.w * w0 + b2.w * w1 + c.w * w2 + d.w * w3;
        } else {
            acc.x += a.x + b2.x + c.x + d.x;
            acc.y += a.y + b2.y + c.y + d.y;
            acc.z += a.z + b2.z + c.z + d.z;
            acc.w += a.w + b2.w + c.w + d.w;
        }
    }
    for (; j < e; j++) {
        int c0 = __ldg(g_csr + j);
        float4 a = __ldg(base + (size_t)c0 * NQ + q);
        float w0 = FIRST ? __ldg(g_dinv + c0) : 1.0f;
        if (FIRST) {
            acc.x += a.x * w0; acc.y += a.y * w0; acc.z += a.z * w0; acc.w += a.w * w0;
        } else {
            acc.x += a.x; acc.y += a.y; acc.z += a.z; acc.w += a.w;
        }
    }

    float sc = LAST ? dvn : dvn * dvn;
    acc.x *= sc; acc.y *= sc; acc.z *= sc; acc.w *= sc;
    if (LAST) {
        int c = __ldg(cl + n);
        red_add_v4(g_xc + (size_t)c * OF + q * 4, acc);
    } else {
        float4* outp = (float4*)(DIR ? g_u : g_v);
        outp[(size_t)n * NQ + q] = acc;
    }
}

// out[n] = xc[cluster[n]] / max(cnt,1) + b
__global__ void k_out(const int* __restrict__ cl, const float* __restrict__ b,
                      float* __restrict__ out) {
    int i = blockIdx.x * blockDim.x + threadIdx.x;
    if (i >= NN * NQ) return;
    int n = i / NQ;
    int q = i - n * NQ;
    int c = __ldg(cl + n);
    float s = 1.0f / (float)max(g_cnt[c], 1);
    float4 t = ((const float4*)g_xc)[c * NQ + q];
    float4 bb = ((const float4*)b)[q];
    float4 o;
    o.x = t.x * s + bb.x;
    o.y = t.y * s + bb.y;
    o.z = t.z * s + bb.z;
    o.w = t.w * s + bb.w;
    ((float4*)out)[i] = o;
}

// side stream + events: created ONCE on the first (correctness, non-captured)
// call via magic static; work per call is identical, so determinism holds.
struct Aux {
    cudaStream_t s2;
    cudaEvent_t ev0, ev2;
    bool ok;
    Aux() {
        ok = (cudaStreamCreateWithFlags(&s2, cudaStreamNonBlocking) == cudaSuccess) &&
             (cudaEventCreateWithFlags(&ev0, cudaEventDisableTiming) == cudaSuccess) &&
             (cudaEventCreateWithFlags(&ev2, cudaEventDisableTiming) == cudaSuccess);
    }
};

extern "C" void kernel_launch(void* const* d_in, const int* in_sizes, int n_in,
                              void* d_out, int out_size) {
    const float* x = nullptr;
    const int* ei = nullptr;
    const int* cl = nullptr;
    const float* W = nullptr;
    const float* b = nullptr;
    for (int i = 0; i < n_in; i++) {
        switch (in_sizes[i]) {
            case NN * INF: x = (const float*)d_in[i]; break;
            case 2 * NE:   ei = (const int*)d_in[i]; break;
            case NN:       cl = (const int*)d_in[i]; break;
            case OF * INF: W = (const float*)d_in[i]; break;
            case OF:       b = (const float*)d_in[i]; break;
            default: break;
        }
    }
    const int* row = ei;        // targets
    const int* col = ei + NE;   // sources

    static Aux aux;             // first call is the (uncaptured) correctness run

    const int B = 256;
    if (aux.ok) {
        // fork at t=0: transform (depends only on x,W) fully overlaps the
        // entire histogram + CSR build on the legacy stream.
        cudaEventRecord(aux.ev0, 0);
        cudaStreamWaitEvent(aux.s2, aux.ev0, 0);
        k_transform<<<(NN + 127) / 128, 128, 0, aux.s2>>>(x, W);
        cudaEventRecord(aux.ev2, aux.s2);

        k_init<<<(NC * OF + B - 1) / B, B>>>();
        k_hist<<<(NE + B - 1) / B, B>>>(row, cl);
        k_scanA<<<SNB, 256>>>();
        k_scanB<<<SNB, 256>>>();
        k_scatter<<<(NE + B - 1) / B, B>>>(row, col);
        cudaStreamWaitEvent(0, aux.ev2, 0);   // join before hops
    } else {
        k_init<<<(NC * OF + B - 1) / B, B>>>();
        k_hist<<<(NE + B - 1) / B, B>>>(row, cl);
        k_scanA<<<SNB, 256>>>();
        k_scanB<<<SNB, 256>>>();
        k_scatter<<<(NE + B - 1) / B, B>>>(row, col);
        k_transform<<<(NN + 127) / 128, 128>>>(x, W);
    }

    const int HG = (NN + 31) / 32;
    k_hop<0, 0, 1><<<HG, 320>>>(cl);   // w -> v   (applies dinv[col] in-gather)
    k_hop<1, 0, 0><<<HG, 320>>>(cl);   // v -> u
    k_hop<0, 1, 0><<<HG, 320>>>(cl);   // u -> cluster sums
    k_out<<<(NN * NQ + B - 1) / B, B>>>(cl, b, (float*)d_out);
}

// round 14
// speedup vs baseline: 1.3257x; 1.3257x over previous
#include <cuda_runtime.h>
#include <cuda_fp16.h>

#define NN 100000     // nodes
#define NE 1600000    // edges
#define INF 64        // input features
#define OF 40         // output features
#define NQ (OF / 4)   // 10 quads per row (quad = 4 features)
#define NC 10000      // clusters
#define SNB ((NN + 1023) / 1024)   // 98 scan blocks (tile = 256 thr * 4 items)

// ---- scratch (device globals; no dynamic allocation allowed) ----
__device__ __align__(16) __half g_uh[NN * OF];   // fp16 feature ping
__device__ __align__(16) __half g_vh[NN * OF];   // fp16 feature pong
__device__ __align__(16) int   g_deg[NN];     // in-edge histogram (no self loop)
__device__ __align__(16) float g_dinv[NN];    // rsqrt(deg+1)
__device__ __align__(16) int   g_off[NN];     // CSR row offsets (exclusive scan of deg)
__device__ __align__(16) int   g_cur[NN];     // scatter cursors
__device__ __align__(16) int   g_csr[NE];     // CSR column (source) indices
__device__ __align__(16) int   g_part[SNB];   // per-block totals
__device__ __align__(16) float g_xc[NC * OF];
__device__ __align__(16) int   g_cnt[NC];

__device__ __forceinline__ void red_add_v4(float* p, float4 v) {
    asm volatile("red.global.add.v4.f32 [%0], {%1,%2,%3,%4};"
                 :: "l"(p), "f"(v.x), "f"(v.y), "f"(v.z), "f"(v.w)
                 : "memory");
}

// zero deg/cnt/xc (kernel, not memset: must be IN the captured graph)
__global__ void k_init() {
    int i = blockIdx.x * blockDim.x + threadIdx.x;
    if (i < NN) g_deg[i] = 0;
    if (i < NC) g_cnt[i] = 0;
    if (i < NC * OF) g_xc[i] = 0.f;
}

__global__ void k_hist(const int* __restrict__ row, const int* __restrict__ cl) {
    int i = blockIdx.x * blockDim.x + threadIdx.x;
    if (i < NE) atomicAdd(&g_deg[__ldg(row + i)], 1);
    if (i < NN) atomicAdd(&g_cnt[__ldg(cl + i)], 1);
}

__global__ void k_dinv() {
    int i = blockIdx.x * blockDim.x + threadIdx.x;
    if (i < NN) g_dinv[i] = rsqrtf((float)(g_deg[i] + 1));
}

// Pass A: per-block exclusive offsets + block totals.
__global__ void __launch_bounds__(256) k_scanA() {
    __shared__ int warp_sums[8];
    int lane = threadIdx.x & 31, wid = threadIdx.x >> 5;
    int idx = blockIdx.x * 1024 + threadIdx.x * 4;

    int4 d = make_int4(0, 0, 0, 0);
    if (idx + 3 < NN) d = *(const int4*)(g_deg + idx);
    else {
        if (idx < NN)     d.x = g_deg[idx];
        if (idx + 1 < NN) d.y = g_deg[idx + 1];
        if (idx + 2 < NN) d.z = g_deg[idx + 2];
    }
    int s3 = d.x + d.y + d.z + d.w;

    int v = s3;
#pragma unroll
    for (int o = 1; o < 32; o <<= 1) {
        int t = __shfl_up_sync(~0u, v, o);
        if (lane >= o) v += t;
    }
    if (lane == 31) warp_sums[wid] = v;
    __syncthreads();
    if (wid == 0) {
        int w = (lane < 8) ? warp_sums[lane] : 0;
#pragma unroll
        for (int o = 1; o < 8; o <<= 1) {
            int t = __shfl_up_sync(~0u, w, o);
            if (lane >= o) w += t;
        }
        if (lane < 8) warp_sums[lane] = w;
    }
    __syncthreads();
    int excl = (v - s3) + (wid ? warp_sums[wid - 1] : 0);

    int e0 = excl, e1 = e0 + d.x, e2 = e1 + d.y, e3 = e2 + d.z;
    if (idx + 3 < NN) {
        *(int4*)(g_off + idx) = make_int4(e0, e1, e2, e3);
    } else {
        int ee[4] = {e0, e1, e2, e3};
        for (int t = 0; t < 4; t++)
            if (idx + t < NN) g_off[idx + t] = ee[t];
    }
    if (threadIdx.x == 0) g_part[blockIdx.x] = warp_sums[7];
}

// Pass B: each block redundantly computes its base from the 98 partials,
// then finalizes g_off and g_cur.
__global__ void __launch_bounds__(256) k_scanB() {
    __shared__ int sh_part[SNB];
    __shared__ int sh_base;
    for (int t = threadIdx.x; t < SNB; t += blockDim.x) sh_part[t] = g_part[t];
    __syncthreads();
    if (threadIdx.x == 0) {
        int base = 0;
        for (int j = 0; j < (int)blockIdx.x; j++) base += sh_part[j];
        sh_base = base;
    }
    __syncthreads();
    int base = sh_base;
    int idx = blockIdx.x * 1024 + threadIdx.x * 4;
    if (idx + 3 < NN) {
        int4 o = *(const int4*)(g_off + idx);
        o.x += base; o.y += base; o.z += base; o.w += base;
        *(int4*)(g_off + idx) = o;
        *(int4*)(g_cur + idx) = o;
    } else {
        for (int t = 0; t < 4; t++)
            if (idx + t < NN) {
                int o = g_off[idx + t] + base;
                g_off[idx + t] = o;
                g_cur[idx + t] = o;
            }
    }
}

__global__ void k_scatter(const int* __restrict__ row, const int* __restrict__ col) {
    int i = blockIdx.x * blockDim.x + threadIdx.x;
    if (i >= NE) return;
    int r = __ldg(row + i);
    int pos = atomicAdd(&g_cur[r], 1);
    g_csr[pos] = __ldg(col + i);
}

// u0 = dinv * (x @ W^T), f32x2 accumulators, fp16 output (80B rows).
__global__ void __launch_bounds__(128) k_transform(const float* __restrict__ x,
                                                   const float* __restrict__ W) {
    __shared__ float Wp[INF * OF];   // f-major: Wp[f*OF + o]
    for (int i = threadIdx.x; i < INF * OF; i += blockDim.x) {
        int f = i / OF, o = i - f * OF;
        Wp[i] = W[o * INF + f];
    }
    __syncthreads();
    int n = blockIdx.x * blockDim.x + threadIdx.x;
    if (n >= NN) return;

    unsigned long long acc[OF / 2];
#pragma unroll
    for (int p = 0; p < OF / 2; p++) acc[p] = 0ull;

    const float4* xp = (const float4*)(x + (size_t)n * INF);
#pragma unroll 1
    for (int fc = 0; fc < INF; fc += 8) {
        float4 a = __ldg(xp + fc / 4);
        float4 b2 = __ldg(xp + fc / 4 + 1);
        float xs[8] = {a.x, a.y, a.z, a.w, b2.x, b2.y, b2.z, b2.w};
#pragma unroll
        for (int ff = 0; ff < 8; ff++) {
            int f = fc + ff;
            unsigned long long xx;
            asm("mov.b64 %0, {%1, %1};" : "=l"(xx) : "f"(xs[ff]));
            const ulonglong2* wrow = (const ulonglong2*)(Wp + f * OF);
#pragma unroll
            for (int p = 0; p < NQ; p++) {
                ulonglong2 w = wrow[p];
                asm("fma.rn.f32x2 %0, %1, %2, %0;" : "+l"(acc[2 * p]) : "l"(w.x), "l"(xx));
                asm("fma.rn.f32x2 %0, %1, %2, %0;" : "+l"(acc[2 * p + 1]) : "l"(w.y), "l"(xx));
            }
        }
    }
    float dv = g_dinv[n];
    // convert 40 fp32 -> 40 fp16 (scaled by dinv), store 5x uint4 (80B row)
    uint4* up = (uint4*)(g_uh + (size_t)n * OF);
#pragma unroll
    for (int p = 0; p < 5; p++) {   // p covers outputs 8p..8p+7 (4 ull accs)
        unsigned r[4];
#pragma unroll
        for (int k = 0; k < 4; k++) {
            float lo = __uint_as_float((unsigned)(acc[4 * p + k] & 0xffffffffull)) * dv;
            float hi = __uint_as_float((unsigned)(acc[4 * p + k] >> 32)) * dv;
            __half2 h = __floats2half2_rn(lo, hi);
            r[k] = *(unsigned*)&h;
        }
        uint4 st; st.x = r[0]; st.y = r[1]; st.z = r[2]; st.w = r[3];
        up[p] = st;
    }
}

// Gather hop over fp16 rows (80B), fp32 accumulation.
// DIR=0: g_uh -> g_vh.  DIR=1: g_vh -> g_uh.  LAST: g_uh -> cluster RED (fp32).
// 10 lanes per node (one uint2 = 4 halves each), 32 nodes per 320-thread block.
template <int DIR, int LAST>
__global__ void __launch_bounds__(320) k_hop(const int* __restrict__ cl) {
    int tid = threadIdx.x;
    int g = tid / NQ;
    int q = tid - g * NQ;
    int n = blockIdx.x * 32 + g;
    if (n >= NN) return;

    const uint2* base = (const uint2*)(DIR ? g_vh : g_uh);
    int s = g_off[n];
    int e = s + g_deg[n];

    uint2 sv = __ldg(base + (size_t)n * NQ + q);  // self loop
    float2 l0 = __half22float2(*reinterpret_cast<__half2*>(&sv.x));
    float2 l1 = __half22float2(*reinterpret_cast<__half2*>(&sv.y));
    float4 acc = make_float4(l0.x, l0.y, l1.x, l1.y);

    int j = s;
    for (; j + 4 <= e; j += 4) {
        int c0 = __ldg(g_csr + j);
        int c1 = __ldg(g_csr + j + 1);
        int c2 = __ldg(g_csr + j + 2);
        int c3 = __ldg(g_csr + j + 3);
        uint2 a = __ldg(base + (size_t)c0 * NQ + q);
        uint2 b = __ldg(base + (size_t)c1 * NQ + q);
        uint2 c = __ldg(base + (size_t)c2 * NQ + q);
        uint2 d = __ldg(base + (size_t)c3 * NQ + q);
        float2 a0 = __half22float2(*reinterpret_cast<__half2*>(&a.x));
        float2 a1 = __half22float2(*reinterpret_cast<__half2*>(&a.y));
        float2 b0 = __half22float2(*reinterpret_cast<__half2*>(&b.x));
        float2 b1 = __half22float2(*reinterpret_cast<__half2*>(&b.y));
        float2 c0f = __half22float2(*reinterpret_cast<__half2*>(&c.x));
        float2 c1f = __half22float2(*reinterpret_cast<__half2*>(&c.y));
        float2 d0 = __half22float2(*reinterpret_cast<__half2*>(&d.x));
        float2 d1 = __half22float2(*reinterpret_cast<__half2*>(&d.y));
        acc.x += a0.x + b0.x + c0f.x + d0.x;
        acc.y += a0.y + b0.y + c0f.y + d0.y;
        acc.z += a1.x + b1.x + c1f.x + d1.x;
        acc.w += a1.y + b1.y + c1f.y + d1.y;
    }
    for (; j < e; j++) {
        int c0 = __ldg(g_csr + j);
        uint2 a = __ldg(base + (size_t)c0 * NQ + q);
        float2 a0 = __half22float2(*reinterpret_cast<__half2*>(&a.x));
        float2 a1 = __half22float2(*reinterpret_cast<__half2*>(&a.y));
        acc.x += a0.x; acc.y += a0.y; acc.z += a1.x; acc.w += a1.y;
    }

    float dv = g_dinv[n];
    float sc = LAST ? dv : dv * dv;
    acc.x *= sc; acc.y *= sc; acc.z *= sc; acc.w *= sc;
    if (LAST) {
        int c = __ldg(cl + n);
        red_add_v4(g_xc + (size_t)c * OF + q * 4, acc);
    } else {
        uint2* outp = (uint2*)(DIR ? g_uh : g_vh);
        __half2 h0 = __floats2half2_rn(acc.x, acc.y);
        __half2 h1 = __floats2half2_rn(acc.z, acc.w);
        uint2 st; st.x = *(unsigned*)&h0; st.y = *(unsigned*)&h1;
        outp[(size_t)n * NQ + q] = st;
    }
}

// out[n] = xc[cluster[n]] / max(cnt,1) + b   (all fp32)
__global__ void k_out(const int* __restrict__ cl, const float* __restrict__ b,
                      float* __restrict__ out) {
    int i = blockIdx.x * blockDim.x + threadIdx.x;
    if (i >= NN * NQ) return;
    int n = i / NQ;
    int q = i - n * NQ;
    int c = __ldg(cl + n);
    float s = 1.0f / (float)max(g_cnt[c], 1);
    float4 t = ((const float4*)g_xc)[c * NQ + q];
    float4 bb = ((const float4*)b)[q];
    float4 o;
    o.x = t.x * s + bb.x;
    o.y = t.y * s + bb.y;
    o.z = t.z * s + bb.z;
    o.w = t.w * s + bb.w;
    ((float4*)out)[i] = o;
}

// side stream + events: created ONCE on the first (correctness, non-captured)
// call via magic static; work per call is identical, so determinism holds.
struct Aux {
    cudaStream_t s2;
    cudaEvent_t ev0, ev2;
    bool ok;
    Aux() {
        ok = (cudaStreamCreateWithFlags(&s2, cudaStreamNonBlocking) == cudaSuccess) &&
             (cudaEventCreateWithFlags(&ev0, cudaEventDisableTiming) == cudaSuccess) &&
             (cudaEventCreateWithFlags(&ev2, cudaEventDisableTiming) == cudaSuccess);
    }
};

extern "C" void kernel_launch(void* const* d_in, const int* in_sizes, int n_in,
                              void* d_out, int out_size) {
    const float* x = nullptr;
    const int* ei = nullptr;
    const int* cl = nullptr;
    const float* W = nullptr;
    const float* b = nullptr;
    for (int i = 0; i < n_in; i++) {
        switch (in_sizes[i]) {
            case NN * INF: x = (const float*)d_in[i]; break;
            case 2 * NE:   ei = (const int*)d_in[i]; break;
            case NN:       cl = (const int*)d_in[i]; break;
            case OF * INF: W = (const float*)d_in[i]; break;
            case OF:       b = (const float*)d_in[i]; break;
            default: break;
        }
    }
    const int* row = ei;        // targets
    const int* col = ei + NE;   // sources

    static Aux aux;             // first call is the (uncaptured) correctness run

    const int B = 256;
    k_init<<<(NC * OF + B - 1) / B, B>>>();
    k_hist<<<(NE + B - 1) / B, B>>>(row, cl);

    if (aux.ok) {
        // R8 schedule: fork AFTER hist — transform overlaps scan+scatter only
        cudaEventRecord(aux.ev0, 0);
        cudaStreamWaitEvent(aux.s2, aux.ev0, 0);
        k_dinv<<<(NN + B - 1) / B, B, 0, aux.s2>>>();
        k_transform<<<(NN + 127) / 128, 128, 0, aux.s2>>>(x, W);
        cudaEventRecord(aux.ev2, aux.s2);

        k_scanA<<<SNB, 256>>>();
        k_scanB<<<SNB, 256>>>();
        k_scatter<<<(NE + B - 1) / B, B>>>(row, col);
        cudaStreamWaitEvent(0, aux.ev2, 0);   // join before hops
    } else {
        k_dinv<<<(NN + B - 1) / B, B>>>();
        k_scanA<<<SNB, 256>>>();
        k_scanB<<<SNB, 256>>>();
        k_scatter<<<(NE + B - 1) / B, B>>>(row, col);
        k_transform<<<(NN + 127) / 128, 128>>>(x, W);
    }

    const int HG = (NN + 31) / 32;
    k_hop<0, 0><<<HG, 320>>>(cl);   // uh -> vh
    k_hop<1, 0><<<HG, 320>>>(cl);   // vh -> uh
    k_hop<0, 1><<<HG, 320>>>(cl);   // uh -> cluster sums (fp32 RED)
    k_out<<<(NN * NQ + B - 1) / B, B>>>(cl, b, (float*)d_out);
}

// round 15
// speedup vs baseline: 1.4097x; 1.0634x over previous
#include <cuda_runtime.h>
#include <cuda_fp16.h>

#define NN 100000     // nodes
#define NE 1600000    // edges
#define INF 64        // input features
#define OF 40         // output features
#define NQ (OF / 4)   // 10 float-quads per row
#define NL 5          // fp16 row = 80B = 5 x uint4 -> 5 lanes per node in hops
#define NC 10000      // clusters
#define SNB ((NN + 1023) / 1024)   // 98 scan blocks (tile = 256 thr * 4 items)

// ---- scratch (device globals; no dynamic allocation allowed) ----
__device__ __align__(16) __half g_uh[NN * OF];   // fp16 feature ping
__device__ __align__(16) __half g_vh[NN * OF];   // fp16 feature pong
__device__ __align__(16) int   g_deg[NN];
__device__ __align__(16) float g_dinv[NN];
__device__ __align__(16) int   g_off[NN];
__device__ __align__(16) int   g_cur[NN];
__device__ __align__(16) int   g_csr[NE];
__device__ __align__(16) int   g_part[SNB];
__device__ __align__(16) float g_xc[NC * OF];
__device__ __align__(16) int   g_cnt[NC];

__device__ __forceinline__ void red_add_v4(float* p, float4 v) {
    asm volatile("red.global.add.v4.f32 [%0], {%1,%2,%3,%4};"
                 :: "l"(p), "f"(v.x), "f"(v.y), "f"(v.z), "f"(v.w)
                 : "memory");
}

__device__ __forceinline__ void acc8(float* a, uint4 v) {
    float2 t;
    t = __half22float2(*reinterpret_cast<__half2*>(&v.x)); a[0] += t.x; a[1] += t.y;
    t = __half22float2(*reinterpret_cast<__half2*>(&v.y)); a[2] += t.x; a[3] += t.y;
    t = __half22float2(*reinterpret_cast<__half2*>(&v.z)); a[4] += t.x; a[5] += t.y;
    t = __half22float2(*reinterpret_cast<__half2*>(&v.w)); a[6] += t.x; a[7] += t.y;
}

// zero deg/cnt/xc (kernel, not memset: must be IN the captured graph)
__global__ void k_init() {
    int i = blockIdx.x * blockDim.x + threadIdx.x;
    if (i < NN) g_deg[i] = 0;
    if (i < NC) g_cnt[i] = 0;
    if (i < NC * OF) g_xc[i] = 0.f;
}

__global__ void k_hist(const int* __restrict__ row, const int* __restrict__ cl) {
    int i = blockIdx.x * blockDim.x + threadIdx.x;
    if (i < NE) atomicAdd(&g_deg[__ldg(row + i)], 1);
    if (i < NN) atomicAdd(&g_cnt[__ldg(cl + i)], 1);
}

__global__ void k_dinv() {
    int i = blockIdx.x * blockDim.x + threadIdx.x;
    if (i < NN) g_dinv[i] = rsqrtf((float)(g_deg[i] + 1));
}

// Pass A: per-block exclusive offsets + block totals.
__global__ void __launch_bounds__(256) k_scanA() {
    __shared__ int warp_sums[8];
    int lane = threadIdx.x & 31, wid = threadIdx.x >> 5;
    int idx = blockIdx.x * 1024 + threadIdx.x * 4;

    int4 d = make_int4(0, 0, 0, 0);
    if (idx + 3 < NN) d = *(const int4*)(g_deg + idx);
    else {
        if (idx < NN)     d.x = g_deg[idx];
        if (idx + 1 < NN) d.y = g_deg[idx + 1];
        if (idx + 2 < NN) d.z = g_deg[idx + 2];
    }
    int s3 = d.x + d.y + d.z + d.w;

    int v = s3;
#pragma unroll
    for (int o = 1; o < 32; o <<= 1) {
        int t = __shfl_up_sync(~0u, v, o);
        if (lane >= o) v += t;
    }
    if (lane == 31) warp_sums[wid] = v;
    __syncthreads();
    if (wid == 0) {
        int w = (lane < 8) ? warp_sums[lane] : 0;
#pragma unroll
        for (int o = 1; o < 8; o <<= 1) {
            int t = __shfl_up_sync(~0u, w, o);
            if (lane >= o) w += t;
        }
        if (lane < 8) warp_sums[lane] = w;
    }
    __syncthreads();
    int excl = (v - s3) + (wid ? warp_sums[wid - 1] : 0);

    int e0 = excl, e1 = e0 + d.x, e2 = e1 + d.y, e3 = e2 + d.z;
    if (idx + 3 < NN) {
        *(int4*)(g_off + idx) = make_int4(e0, e1, e2, e3);
    } else {
        int ee[4] = {e0, e1, e2, e3};
        for (int t = 0; t < 4; t++)
            if (idx + t < NN) g_off[idx + t] = ee[t];
    }
    if (threadIdx.x == 0) g_part[blockIdx.x] = warp_sums[7];
}

// Pass B: redundant per-block base from the 98 partials; finalize off + cur.
__global__ void __launch_bounds__(256) k_scanB() {
    __shared__ int sh_part[SNB];
    __shared__ int sh_base;
    for (int t = threadIdx.x; t < SNB; t += blockDim.x) sh_part[t] = g_part[t];
    __syncthreads();
    if (threadIdx.x == 0) {
        int base = 0;
        for (int j = 0; j < (int)blockIdx.x; j++) base += sh_part[j];
        sh_base = base;
    }
    __syncthreads();
    int base = sh_base;
    int idx = blockIdx.x * 1024 + threadIdx.x * 4;
    if (idx + 3 < NN) {
        int4 o = *(const int4*)(g_off + idx);
        o.x += base; o.y += base; o.z += base; o.w += base;
        *(int4*)(g_off + idx) = o;
        *(int4*)(g_cur + idx) = o;
    } else {
        for (int t = 0; t < 4; t++)
            if (idx + t < NN) {
                int o = g_off[idx + t] + base;
                g_off[idx + t] = o;
                g_cur[idx + t] = o;
            }
    }
}

__global__ void k_scatter(const int* __restrict__ row, const int* __restrict__ col) {
    int i = blockIdx.x * blockDim.x + threadIdx.x;
    if (i >= NE) return;
    int r = __ldg(row + i);
    int pos = atomicAdd(&g_cur[r], 1);
    g_csr[pos] = __ldg(col + i);
}

// u0 = dinv * (x @ W^T). TWO nodes per thread with SCALAR f32 accumulators
// (80 acc regs — unlike R10's 160-reg f32x2 attempt): each 16B W smem read
// feeds FMAs for both nodes -> LDS traffic (the measured limiter) halves.
// n0 = blk*512 + t, n1 = n0 + 256; fp16 output rows (80B).
__global__ void __launch_bounds__(256) k_transform(const float* __restrict__ x,
                                                   const float* __restrict__ W) {
    __shared__ float4 Wp[INF * NQ];   // f-major: Wp[f*NQ+p] = W[4p..4p+3][f]
    for (int i = threadIdx.x; i < INF * NQ; i += blockDim.x) {
        int f = i / NQ, oq = i - f * NQ;
        Wp[i] = make_float4(W[(4 * oq + 0) * INF + f], W[(4 * oq + 1) * INF + f],
                            W[(4 * oq + 2) * INF + f], W[(4 * oq + 3) * INF + f]);
    }
    __syncthreads();
    int n0 = blockIdx.x * 512 + threadIdx.x;
    int n1 = n0 + 256;
    if (n0 >= NN) return;
    bool has1 = (n1 < NN);

    float a0[OF], a1[OF];
#pragma unroll
    for (int k = 0; k < OF; k++) { a0[k] = 0.f; a1[k] = 0.f; }

    const float4* xp0 = (const float4*)(x + (size_t)n0 * INF);
    const float4* xp1 = (const float4*)(x + (size_t)n1 * INF);
#pragma unroll 1
    for (int fc = 0; fc < INF; fc += 4) {
        float4 va = __ldg(xp0 + fc / 4);
        float4 vb = has1 ? __ldg(xp1 + fc / 4) : make_float4(0.f, 0.f, 0.f, 0.f);
        float xs0[4] = {va.x, va.y, va.z, va.w};
        float xs1[4] = {vb.x, vb.y, vb.z, vb.w};
#pragma unroll
        for (int ff = 0; ff < 4; ff++) {
            float s0 = xs0[ff], s1 = xs1[ff];
            const float4* wrow = &Wp[(fc + ff) * NQ];
#pragma unroll
            for (int p = 0; p < NQ; p++) {
                float4 w = wrow[p];
                a0[4 * p + 0] += s0 * w.x; a1[4 * p + 0] += s1 * w.x;
                a0[4 * p + 1] += s0 * w.y; a1[4 * p + 1] += s1 * w.y;
                a0[4 * p + 2] += s0 * w.z; a1[4 * p + 2] += s1 * w.z;
                a0[4 * p + 3] += s0 * w.w; a1[4 * p + 3] += s1 * w.w;
            }
        }
    }
    {
        float dv = g_dinv[n0];
        uint4* up = (uint4*)(g_uh + (size_t)n0 * OF);
#pragma unroll
        for (int p = 0; p < 5; p++) {
            __half2 h0 = __floats2half2_rn(a0[8 * p + 0] * dv, a0[8 * p + 1] * dv);
            __half2 h1 = __floats2half2_rn(a0[8 * p + 2] * dv, a0[8 * p + 3] * dv);
            __half2 h2 = __floats2half2_rn(a0[8 * p + 4] * dv, a0[8 * p + 5] * dv);
            __half2 h3 = __floats2half2_rn(a0[8 * p + 6] * dv, a0[8 * p + 7] * dv);
            uint4 st;
            st.x = *(unsigned*)&h0; st.y = *(unsigned*)&h1;
            st.z = *(unsigned*)&h2; st.w = *(unsigned*)&h3;
            up[p] = st;
        }
    }
    if (has1) {
        float dv = g_dinv[n1];
        uint4* up = (uint4*)(g_uh + (size_t)n1 * OF);
#pragma unroll
        for (int p = 0; p < 5; p++) {
            __half2 h0 = __floats2half2_rn(a1[8 * p + 0] * dv, a1[8 * p + 1] * dv);
            __half2 h1 = __floats2half2_rn(a1[8 * p + 2] * dv, a1[8 * p + 3] * dv);
            __half2 h2 = __floats2half2_rn(a1[8 * p + 4] * dv, a1[8 * p + 5] * dv);
            __half2 h3 = __floats2half2_rn(a1[8 * p + 6] * dv, a1[8 * p + 7] * dv);
            uint4 st;
            st.x = *(unsigned*)&h0; st.y = *(unsigned*)&h1;
            st.z = *(unsigned*)&h2; st.w = *(unsigned*)&h3;
            up[p] = st;
        }
    }
}

// Gather hop over fp16 rows, fp32 accumulation. 5 lanes per node, one uint4
// (8 halves) each -> HALF the LDG instructions per edge vs 10x uint2.
// 64 nodes per 320-thread block.
// DIR=0: g_uh -> g_vh.  DIR=1: g_vh -> g_uh.  LAST: g_uh -> cluster RED (fp32).
template <int DIR, int LAST>
__global__ void __launch_bounds__(320) k_hop(const int* __restrict__ cl) {
    int tid = threadIdx.x;
    int g = tid / NL;
    int q = tid - g * NL;
    int n = blockIdx.x * 64 + g;
    if (n >= NN) return;

    const uint4* base = (const uint4*)(DIR ? g_vh : g_uh);
    int s = g_off[n];
    int e = s + g_deg[n];

    float acc[8] = {0.f, 0.f, 0.f, 0.f, 0.f, 0.f, 0.f, 0.f};
    acc8(acc, __ldg(base + (size_t)n * NL + q));   // self loop

    int j = s;
    for (; j + 4 <= e; j += 4) {
        int c0 = __ldg(g_csr + j);
        int c1 = __ldg(g_csr + j + 1);
        int c2 = __ldg(g_csr + j + 2);
        int c3 = __ldg(g_csr + j + 3);
        uint4 a = __ldg(base + (size_t)c0 * NL + q);
        uint4 b = __ldg(base + (size_t)c1 * NL + q);
        uint4 c = __ldg(base + (size_t)c2 * NL + q);
        uint4 d = __ldg(base + (size_t)c3 * NL + q);
        acc8(acc, a); acc8(acc, b); acc8(acc, c); acc8(acc, d);
    }
    for (; j < e; j++) {
        int c0 = __ldg(g_csr + j);
        acc8(acc, __ldg(base + (size_t)c0 * NL + q));
    }

    float dv = g_dinv[n];
    float sc = LAST ? dv : dv * dv;
#pragma unroll
    for (int k = 0; k < 8; k++) acc[k] *= sc;

    if (LAST) {
        int c = __ldg(cl + n);
        float* dst = g_xc + (size_t)c * OF + q * 8;
        red_add_v4(dst, make_float4(acc[0], acc[1], acc[2], acc[3]));
        red_add_v4(dst + 4, make_float4(acc[4], acc[5], acc[6], acc[7]));
    } else {
        uint4* outp = (uint4*)(DIR ? g_uh : g_vh);
        __half2 h0 = __floats2half2_rn(acc[0], acc[1]);
        __half2 h1 = __floats2half2_rn(acc[2], acc[3]);
        __half2 h2 = __floats2half2_rn(acc[4], acc[5]);
        __half2 h3 = __floats2half2_rn(acc[6], acc[7]);
        uint4 st;
        st.x = *(unsigned*)&h0; st.y = *(unsigned*)&h1;
        st.z = *(unsigned*)&h2; st.w = *(unsigned*)&h3;
        outp[(size_t)n * NL + q] = st;
    }
}

// out[n] = xc[cluster[n]] / max(cnt,1) + b   (all fp32)
__global__ void k_out(const int* __restrict__ cl, const float* __restrict__ b,
                      float* __restrict__ out) {
    int i = blockIdx.x * blockDim.x + threadIdx.x;
    if (i >= NN * NQ) return;
    int n = i / NQ;
    int q = i - n * NQ;
    int c = __ldg(cl + n);
    float s = 1.0f / (float)max(g_cnt[c], 1);
    float4 t = ((const float4*)g_xc)[c * NQ + q];
    float4 bb = ((const float4*)b)[q];
    float4 o;
    o.x = t.x * s + bb.x;
    o.y = t.y * s + bb.y;
    o.z = t.z * s + bb.z;
    o.w = t.w * s + bb.w;
    ((float4*)out)[i] = o;
}

// side stream + events: created ONCE on the first (correctness, non-captured)
// call via magic static; work per call is identical, so determinism holds.
struct Aux {
    cudaStream_t s2;
    cudaEvent_t ev0, ev2;
    bool ok;
    Aux() {
        ok = (cudaStreamCreateWithFlags(&s2, cudaStreamNonBlocking) == cudaSuccess) &&
             (cudaEventCreateWithFlags(&ev0, cudaEventDisableTiming) == cudaSuccess) &&
             (cudaEventCreateWithFlags(&ev2, cudaEventDisableTiming) == cudaSuccess);
    }
};

extern "C" void kernel_launch(void* const* d_in, const int* in_sizes, int n_in,
                              void* d_out, int out_size) {
    const float* x = nullptr;
    const int* ei = nullptr;
    const int* cl = nullptr;
    const float* W = nullptr;
    const float* b = nullptr;
    for (int i = 0; i < n_in; i++) {
        switch (in_sizes[i]) {
            case NN * INF: x = (const float*)d_in[i]; break;
            case 2 * NE:   ei = (const int*)d_in[i]; break;
            case NN:       cl = (const int*)d_in[i]; break;
            case OF * INF: W = (const float*)d_in[i]; break;
            case OF:       b = (const float*)d_in[i]; break;
            default: break;
        }
    }
    const int* row = ei;        // targets
    const int* col = ei + NE;   // sources

    static Aux aux;             // first call is the (uncaptured) correctness run

    const int B = 256;
    k_init<<<(NC * OF + B - 1) / B, B>>>();
    k_hist<<<(NE + B - 1) / B, B>>>(row, cl);

    const int TG = (NN + 511) / 512;
    if (aux.ok) {
        // R8/R14 schedule: fork AFTER hist — transform overlaps scan+scatter
        cudaEventRecord(aux.ev0, 0);
        cudaStreamWaitEvent(aux.s2, aux.ev0, 0);
        k_dinv<<<(NN + B - 1) / B, B, 0, aux.s2>>>();
        k_transform<<<TG, 256, 0, aux.s2>>>(x, W);
        cudaEventRecord(aux.ev2, aux.s2);

        k_scanA<<<SNB, 256>>>();
        k_scanB<<<SNB, 256>>>();
        k_scatter<<<(NE + B - 1) / B, B>>>(row, col);
        cudaStreamWaitEvent(0, aux.ev2, 0);   // join before hops
    } else {
        k_dinv<<<(NN + B - 1) / B, B>>>();
        k_scanA<<<SNB, 256>>>();
        k_scanB<<<SNB, 256>>>();
        k_scatter<<<(NE + B - 1) / B, B>>>(row, col);
        k_transform<<<TG, 256>>>(x, W);
    }

    const int HG = (NN + 63) / 64;
    k_hop<0, 0><<<HG, 320>>>(cl);   // uh -> vh
    k_hop<1, 0><<<HG, 320>>>(cl);   // vh -> uh
    k_hop<0, 1><<<HG, 320>>>(cl);   // uh -> cluster sums (fp32 RED)
    k_out<<<(NN * NQ + B - 1) / B, B>>>(cl, b, (float*)d_out);
}